// round 11
// baseline (speedup 1.0000x reference)
#include <cuda_runtime.h>

// GRU autoencoder: B=128, H=512, T=512 enc + 513 dec iterations.
// Persistent single kernel. 128 CTAs, CTA c owns hidden cols [4c,4c+4).
//
// R10 -> R11: NTH 512 -> 1024 (8 warps/SMSP), K split 8 ways (64/thread).
// Two-stage SMEM reduction (octants 4-7 publish, quarters 0-3 combine
// in place), distributed epilogue (one (b,jj) output per quarter-thread),
// fast tanh via __expf. s_w/s_lin/s_red in dynamic SMEM (53.2 KB).

#define HH   512
#define TT   512
#define BB   128
#define NBLK 128
#define COLS 4
#define NTH  1024
#define KPT  64            // K per thread

#define SMEM_FLOATS (13 * HH + 4 * 13 * BB)   // s_w(12 rows)+s_lin + s_red
#define SMEM_BYTES  (SMEM_FLOATS * 4)

__device__ float g_hA[HH * BB];
__device__ float g_hB[HH * BB];
__device__ unsigned long long g_arrive;   // monotonic; replay-safe
__device__ unsigned long long g_release;

__device__ __forceinline__ void grid_barrier() {
    __threadfence();
    __syncthreads();
    if (threadIdx.x == 0) {
        unsigned long long t = atomicAdd(&g_arrive, 1ULL) + 1ULL;
        unsigned long long phase = (t + (unsigned long long)(NBLK - 1)) / NBLK;
        if ((t % NBLK) == 0ULL) {
            atomicAdd(&g_release, 1ULL);
        } else {
            long long guard = 0;
            while (*(volatile unsigned long long*)&g_release < phase) {
                __nanosleep(20);
                if (++guard > 900000000LL) __trap();   // fail loud, never hang
            }
        }
        __threadfence();
    }
    __syncthreads();
}

__device__ __forceinline__ float sigf(float v) {
    return __fdividef(1.0f, 1.0f + __expf(-v));
}
__device__ __forceinline__ float ftanh(float v) {
    float e = __expf(-2.0f * v);
    return __fdividef(1.0f - e, 1.0f + e);
}

__device__ __forceinline__ unsigned long long pack2(float lo, float hi) {
    unsigned long long r;
    asm("mov.b64 %0, {%1, %2};" : "=l"(r) : "f"(lo), "f"(hi));
    return r;
}
__device__ __forceinline__ unsigned long long fma2(unsigned long long a,
                                                   unsigned long long b,
                                                   unsigned long long c) {
    unsigned long long d;
    asm("fma.rn.f32x2 %0, %1, %2, %3;" : "=l"(d) : "l"(a), "l"(b), "l"(c));
    return d;
}
__device__ __forceinline__ float red2(unsigned long long v) {
    float lo, hi;
    asm("mov.b64 {%0, %1}, %2;" : "=f"(lo), "=f"(hi) : "l"(v));
    return lo + hi;
}

__global__ void __launch_bounds__(NTH, 1)
gru_ae(const float* __restrict__ x,
       const float* __restrict__ eWi, const float* __restrict__ eWh,
       const float* __restrict__ ebi, const float* __restrict__ ebh,
       const float* __restrict__ dWi, const float* __restrict__ dWh,
       const float* __restrict__ dbi, const float* __restrict__ dbh,
       const float* __restrict__ lW,  const float* __restrict__ lb,
       float* __restrict__ out)
{
    extern __shared__ __align__(16) float smem[];
    float* s_w   = smem;                 // 12*HH: Wh rows, row = jj*3+gate
    float* s_lin = smem + 12 * HH;       // HH
    float* s_red = smem + 13 * HH;       // 4 quarters x 13 x BB

    __shared__ float s_wi[12], s_bi[12], s_bh[12];
    __shared__ float s_lb;

    const int tid = threadIdx.x;
    const int b   = tid & (BB - 1);
    const int ko  = tid >> 7;            // k-octant: 0..7
    const int j0  = blockIdx.x * COLS;

    // ---- encoder weights -> SMEM (vectorized rows) ----
    for (int i = tid; i < 12 * (HH / 4); i += NTH) {
        int gl = i / (HH / 4), kk = i % (HH / 4);
        int grow = (gl % 3) * HH + (j0 + gl / 3);
        ((float4*)s_w)[gl * (HH / 4) + kk] = ((const float4*)eWh)[grow * (HH / 4) + kk];
    }
    for (int i = tid; i < HH / 4; i += NTH)
        ((float4*)s_lin)[i] = ((const float4*)lW)[i];
    if (tid < 12) {
        int grow = (tid % 3) * HH + (j0 + tid / 3);
        s_wi[tid] = eWi[grow];
        s_bi[tid] = ebi[grow];
        s_bh[tid] = ebh[grow];
    }
    if (tid == 0) s_lb = lb[0];

    for (int i = tid; i < COLS * BB; i += NTH) g_hA[j0 * BB + i] = 0.0f;

    grid_barrier();

    float* hcur = g_hA;
    float* hnxt = g_hB;

    // ================= encoder: 512 steps =================
    for (int t = 0; t < TT; ++t) {
        unsigned long long acc[12];
        #pragma unroll
        for (int g = 0; g < 12; ++g) acc[g] = 0ULL;

        const int k0 = ko * KPT;
        #pragma unroll 2
        for (int k = k0; k < k0 + KPT; k += 4) {
            float h0 = __ldcg(&hcur[(k + 0) * BB + b]);
            float h1 = __ldcg(&hcur[(k + 1) * BB + b]);
            float h2 = __ldcg(&hcur[(k + 2) * BB + b]);
            float h3 = __ldcg(&hcur[(k + 3) * BB + b]);
            unsigned long long ha = pack2(h0, h1);
            unsigned long long hb = pack2(h2, h3);
            #pragma unroll
            for (int g = 0; g < 12; ++g) {
                const ulonglong2 w2 = *(const ulonglong2*)&s_w[g * HH + k];
                acc[g] = fma2(ha, w2.x, acc[g]);
                acc[g] = fma2(hb, w2.y, acc[g]);
            }
        }

        // stage A: octants 4..7 publish partials into quarter slot (ko-4)
        if (ko >= 4) {
            float* dst = &s_red[((ko - 4) * 13) * BB + b];
            #pragma unroll
            for (int g = 0; g < 12; ++g) dst[g * BB] = red2(acc[g]);
        }
        __syncthreads();

        // stage B: quarters 0..3 combine own + partner octant, publish
        // gates belonging to OTHER quarters (own 3 stay in registers)
        float q[12];
        if (ko < 4) {
            float* row = &s_red[(ko * 13) * BB + b];
            #pragma unroll
            for (int g = 0; g < 12; ++g) q[g] = red2(acc[g]) + row[g * BB];
            #pragma unroll
            for (int g = 0; g < 12; ++g)
                if (g / 3 != ko) row[g * BB] = q[g];
        }
        __syncthreads();

        // distributed epilogue: thread (ko<4, b) owns output (jj=ko, b)
        if (ko < 4) {
            const int g0 = 3 * ko;
            float ar = q[g0 + 0], az = q[g0 + 1], an = q[g0 + 2];
            #pragma unroll
            for (int qq = 0; qq < 4; ++qq) {
                if (qq != ko) {
                    ar += s_red[(qq * 13 + g0 + 0) * BB + b];
                    az += s_red[(qq * 13 + g0 + 1) * BB + b];
                    an += s_red[(qq * 13 + g0 + 2) * BB + b];
                }
            }
            float xv = x[b * TT + t];
            float r = sigf(fmaf(xv, s_wi[g0 + 0], s_bi[g0 + 0] + s_bh[g0 + 0]) + ar);
            float z = sigf(fmaf(xv, s_wi[g0 + 1], s_bi[g0 + 1] + s_bh[g0 + 1]) + az);
            float n = ftanh(fmaf(xv, s_wi[g0 + 2], s_bi[g0 + 2]) + r * (an + s_bh[g0 + 2]));
            float hp = __ldcg(&hcur[(j0 + ko) * BB + b]);
            hnxt[(j0 + ko) * BB + b] = (1.0f - z) * n + z * hp;
        }

        grid_barrier();
        float* tc = hcur; hcur = hnxt; hnxt = tc;
    }

    // ---- swap SMEM weights to decoder ----
    for (int i = tid; i < 12 * (HH / 4); i += NTH) {
        int gl = i / (HH / 4), kk = i % (HH / 4);
        int grow = (gl % 3) * HH + (j0 + gl / 3);
        ((float4*)s_w)[gl * (HH / 4) + kk] = ((const float4*)dWh)[grow * (HH / 4) + kk];
    }
    if (tid < 12) {
        int grow = (tid % 3) * HH + (j0 + tid / 3);
        s_wi[tid] = dWi[grow];
        s_bi[tid] = dbi[grow];
        s_bh[tid] = dbh[grow];
    }
    __syncthreads();

    // ================= decoder: i = 0..512 =================
    // y_i = h_i @ lin_W.T + lin_b (13th accumulator, redundant per CTA).
    // Emit y_i at out[:, T-i] for i>=1. For i<512 also compute h_{i+1}.
    for (int i = 0; i <= TT; ++i) {
        unsigned long long acc[13];
        #pragma unroll
        for (int g = 0; g < 13; ++g) acc[g] = 0ULL;

        const int k0 = ko * KPT;
        #pragma unroll 2
        for (int k = k0; k < k0 + KPT; k += 4) {
            float h0 = __ldcg(&hcur[(k + 0) * BB + b]);
            float h1 = __ldcg(&hcur[(k + 1) * BB + b]);
            float h2 = __ldcg(&hcur[(k + 2) * BB + b]);
            float h3 = __ldcg(&hcur[(k + 3) * BB + b]);
            unsigned long long ha = pack2(h0, h1);
            unsigned long long hb = pack2(h2, h3);
            #pragma unroll
            for (int g = 0; g < 12; ++g) {
                const ulonglong2 w2 = *(const ulonglong2*)&s_w[g * HH + k];
                acc[g] = fma2(ha, w2.x, acc[g]);
                acc[g] = fma2(hb, w2.y, acc[g]);
            }
            const ulonglong2 l2 = *(const ulonglong2*)&s_lin[k];
            acc[12] = fma2(ha, l2.x, acc[12]);
            acc[12] = fma2(hb, l2.y, acc[12]);
        }

        if (ko >= 4) {
            float* dst = &s_red[((ko - 4) * 13) * BB + b];
            #pragma unroll
            for (int g = 0; g < 13; ++g) dst[g * BB] = red2(acc[g]);
        }
        __syncthreads();

        float q[13];
        if (ko < 4) {
            float* row = &s_red[(ko * 13) * BB + b];
            #pragma unroll
            for (int g = 0; g < 13; ++g) q[g] = red2(acc[g]) + row[g * BB];
            #pragma unroll
            for (int g = 0; g < 12; ++g)
                if (g / 3 != ko) row[g * BB] = q[g];
            row[12 * BB] = q[12];          // y partial: all quarters need it
        }
        __syncthreads();

        if (ko < 4) {
            float y = q[12];
            #pragma unroll
            for (int qq = 0; qq < 4; ++qq)
                if (qq != ko) y += s_red[(qq * 13 + 12) * BB + b];
            y += s_lb;
            if (i >= 1 && blockIdx.x == 0 && ko == 0) out[b * TT + (TT - i)] = y;
            if (i < TT) {
                const int g0 = 3 * ko;
                float ar = q[g0 + 0], az = q[g0 + 1], an = q[g0 + 2];
                #pragma unroll
                for (int qq = 0; qq < 4; ++qq) {
                    if (qq != ko) {
                        ar += s_red[(qq * 13 + g0 + 0) * BB + b];
                        az += s_red[(qq * 13 + g0 + 1) * BB + b];
                        an += s_red[(qq * 13 + g0 + 2) * BB + b];
                    }
                }
                float r = sigf(fmaf(y, s_wi[g0 + 0], s_bi[g0 + 0] + s_bh[g0 + 0]) + ar);
                float z = sigf(fmaf(y, s_wi[g0 + 1], s_bi[g0 + 1] + s_bh[g0 + 1]) + az);
                float n = ftanh(fmaf(y, s_wi[g0 + 2], s_bi[g0 + 2]) + r * (an + s_bh[g0 + 2]));
                float hp = __ldcg(&hcur[(j0 + ko) * BB + b]);
                hnxt[(j0 + ko) * BB + b] = (1.0f - z) * n + z * hp;
            }
        }

        if (i < TT) {
            grid_barrier();
            float* tc = hcur; hcur = hnxt; hnxt = tc;
        }
    }
}

extern "C" void kernel_launch(void* const* d_in, const int* in_sizes, int n_in,
                              void* d_out, int out_size) {
    cudaFuncSetAttribute(gru_ae, cudaFuncAttributeMaxDynamicSharedMemorySize,
                         SMEM_BYTES);
    gru_ae<<<NBLK, NTH, SMEM_BYTES>>>(
        (const float*)d_in[0],
        (const float*)d_in[1], (const float*)d_in[2],
        (const float*)d_in[3], (const float*)d_in[4],
        (const float*)d_in[5], (const float*)d_in[6],
        (const float*)d_in[7], (const float*)d_in[8],
        (const float*)d_in[9], (const float*)d_in[10],
        (float*)d_out);
}

// round 12
// speedup vs baseline: 1.2399x; 1.2399x over previous
#include <cuda_runtime.h>

// GRU autoencoder: B=128, H=512, T=512 enc + 513 dec iterations.
// Persistent single kernel, 128 CTAs, CTA c owns hidden cols [4c,4c+4).
//
// R11 -> R12: revert to 512 threads (4 warps/SMSP, ~124 regs — R11's 1024thr
// /64-reg config regressed). h stored as float4 over k (one LDG.128 replaces
// 4 LDG.32; halves of the 16B load feed fma.f32x2 directly). Fully
// distributed epilogue (all 512 threads: one (col,b) output each),
// publish-all SMEM reduction, early hp/x loads, fast tanh.

#define HH   512
#define TT   512
#define BB   128
#define NBLK 128
#define COLS 4
#define NTH  512
#define MQ   32            // float4-slots (of 4 k) per thread quarter

typedef unsigned long long ull;

#define SMEM_FLOATS (13 * HH + 4 * 13 * BB)
#define SMEM_BYTES  (SMEM_FLOATS * 4)

__device__ float4 g_hA[HH * BB / 4];     // slot m*BB+b = h[4m..4m+3][b]
__device__ float4 g_hB[HH * BB / 4];
__device__ unsigned long long g_arrive;  // monotonic; replay-safe
__device__ unsigned long long g_release;

__device__ __forceinline__ void grid_barrier() {
    __threadfence();
    __syncthreads();
    if (threadIdx.x == 0) {
        unsigned long long t = atomicAdd(&g_arrive, 1ULL) + 1ULL;
        unsigned long long phase = (t + (unsigned long long)(NBLK - 1)) / NBLK;
        if ((t % NBLK) == 0ULL) {
            atomicAdd(&g_release, 1ULL);
        } else {
            long long guard = 0;
            while (*(volatile unsigned long long*)&g_release < phase) {
                __nanosleep(20);
                if (++guard > 900000000LL) __trap();
            }
        }
        __threadfence();
    }
    __syncthreads();
}

__device__ __forceinline__ float sigf(float v) {
    return __fdividef(1.0f, 1.0f + __expf(-v));
}
__device__ __forceinline__ float ftanh(float v) {
    float e = __expf(-2.0f * v);
    return __fdividef(1.0f - e, 1.0f + e);
}

__device__ __forceinline__ ull pack2(float lo, float hi) {
    ull r;
    asm("mov.b64 %0, {%1, %2};" : "=l"(r) : "f"(lo), "f"(hi));
    return r;
}
__device__ __forceinline__ ull fma2(ull a, ull b, ull c) {
    ull d;
    asm("fma.rn.f32x2 %0, %1, %2, %3;" : "=l"(d) : "l"(a), "l"(b), "l"(c));
    return d;
}
__device__ __forceinline__ float red2(ull v) {
    float lo, hi;
    asm("mov.b64 {%0, %1}, %2;" : "=f"(lo), "=f"(hi) : "l"(v));
    return lo + hi;
}

// 12 gate dots over one 4-chunk block (16 k), given packed h halves
template<int NG>
__device__ __forceinline__ void dot_block(ull* acc, const float* s_w, int m,
                                          ull a0, ull b0, ull a1, ull b1,
                                          ull a2, ull b2, ull a3, ull b3) {
    #pragma unroll
    for (int g = 0; g < NG; ++g) {
        const ulonglong2* wr = (const ulonglong2*)&s_w[g * HH + 4 * m];
        ull t = acc[g];
        t = fma2(a0, wr[0].x, t); t = fma2(b0, wr[0].y, t);
        t = fma2(a1, wr[1].x, t); t = fma2(b1, wr[1].y, t);
        t = fma2(a2, wr[2].x, t); t = fma2(b2, wr[2].y, t);
        t = fma2(a3, wr[3].x, t); t = fma2(b3, wr[3].y, t);
        acc[g] = t;
    }
}

__global__ void __launch_bounds__(NTH, 1)
gru_ae(const float* __restrict__ x,
       const float* __restrict__ eWi, const float* __restrict__ eWh,
       const float* __restrict__ ebi, const float* __restrict__ ebh,
       const float* __restrict__ dWi, const float* __restrict__ dWh,
       const float* __restrict__ dbi, const float* __restrict__ dbh,
       const float* __restrict__ lW,  const float* __restrict__ lb,
       float* __restrict__ out)
{
    extern __shared__ __align__(16) float smem[];
    float* s_w   = smem;                 // 12*HH: Wh rows, row = q*3+gate
    float* s_lin = smem + 12 * HH;       // HH
    float* s_red = smem + 13 * HH;       // [q][13][BB]

    __shared__ float s_wi[12], s_bi[12], s_bh[12];
    __shared__ float s_lb;

    const int tid = threadIdx.x;
    const int b   = tid & (BB - 1);
    const int kq  = tid >> 7;            // quarter 0..3; owns col j0+kq
    const int bx  = blockIdx.x;
    const int j0  = bx * COLS;
    const int g0  = 3 * kq;

    // ---- encoder weights -> SMEM ----
    for (int i = tid; i < 12 * (HH / 4); i += NTH) {
        int gl = i / (HH / 4), kk = i % (HH / 4);
        int grow = (gl % 3) * HH + (j0 + gl / 3);
        ((float4*)s_w)[gl * (HH / 4) + kk] = ((const float4*)eWh)[grow * (HH / 4) + kk];
    }
    for (int i = tid; i < HH / 4; i += NTH)
        ((float4*)s_lin)[i] = ((const float4*)lW)[i];
    if (tid < 12) {
        int grow = (tid % 3) * HH + (j0 + tid / 3);
        s_wi[tid] = eWi[grow];
        s_bi[tid] = ebi[grow];
        s_bh[tid] = ebh[grow];
    }
    if (tid == 0) s_lb = lb[0];

    if (tid < BB) g_hA[bx * BB + tid] = make_float4(0.f, 0.f, 0.f, 0.f);

    grid_barrier();

    float4* hcur = g_hA;
    float4* hnxt = g_hB;

    // ================= encoder: 512 steps =================
    for (int t = 0; t < TT; ++t) {
        // early loads (off the critical dot chain)
        float hp = __ldcg((const float*)(hcur + bx * BB + b) + kq);
        float xv = x[b * TT + t];

        ull acc[12];
        #pragma unroll
        for (int g = 0; g < 12; ++g) acc[g] = 0ULL;

        const int m0 = kq * MQ;
        #pragma unroll 2
        for (int mb = 0; mb < MQ / 4; ++mb) {
            int m = m0 + mb * 4;
            float4 f0 = __ldcg(hcur + (m + 0) * BB + b);
            float4 f1 = __ldcg(hcur + (m + 1) * BB + b);
            float4 f2 = __ldcg(hcur + (m + 2) * BB + b);
            float4 f3 = __ldcg(hcur + (m + 3) * BB + b);
            dot_block<12>(acc, s_w, m,
                          pack2(f0.x, f0.y), pack2(f0.z, f0.w),
                          pack2(f1.x, f1.y), pack2(f1.z, f1.w),
                          pack2(f2.x, f2.y), pack2(f2.z, f2.w),
                          pack2(f3.x, f3.y), pack2(f3.z, f3.w));
        }

        // publish all 12 partials
        {
            float* dst = &s_red[(kq * 13) * BB + b];
            #pragma unroll
            for (int g = 0; g < 12; ++g) dst[g * BB] = red2(acc[g]);
        }
        __syncthreads();

        // every thread owns one output (col j0+kq, batch b)
        {
            float ar = 0.f, az = 0.f, an = 0.f;
            #pragma unroll
            for (int qq = 0; qq < 4; ++qq) {
                ar += s_red[(qq * 13 + g0 + 0) * BB + b];
                az += s_red[(qq * 13 + g0 + 1) * BB + b];
                an += s_red[(qq * 13 + g0 + 2) * BB + b];
            }
            float r = sigf(fmaf(xv, s_wi[g0 + 0], s_bi[g0 + 0] + s_bh[g0 + 0]) + ar);
            float z = sigf(fmaf(xv, s_wi[g0 + 1], s_bi[g0 + 1] + s_bh[g0 + 1]) + az);
            float n = ftanh(fmaf(xv, s_wi[g0 + 2], s_bi[g0 + 2]) + r * (an + s_bh[g0 + 2]));
            ((float*)(hnxt + bx * BB + b))[kq] = (1.0f - z) * n + z * hp;
        }

        grid_barrier();
        float4* tc = hcur; hcur = hnxt; hnxt = tc;
    }

    // ---- swap SMEM weights to decoder ----
    for (int i = tid; i < 12 * (HH / 4); i += NTH) {
        int gl = i / (HH / 4), kk = i % (HH / 4);
        int grow = (gl % 3) * HH + (j0 + gl / 3);
        ((float4*)s_w)[gl * (HH / 4) + kk] = ((const float4*)dWh)[grow * (HH / 4) + kk];
    }
    if (tid < 12) {
        int grow = (tid % 3) * HH + (j0 + tid / 3);
        s_wi[tid] = dWi[grow];
        s_bi[tid] = dbi[grow];
        s_bh[tid] = dbh[grow];
    }
    __syncthreads();

    // ================= decoder: i = 0..512 =================
    // y_i = h_i @ lin_W.T + lin_b (13th acc, redundant). Emit y_i at
    // out[:, T-i] for i>=1. For i<512 also compute h_{i+1}.
    for (int i = 0; i <= TT; ++i) {
        float hp = __ldcg((const float*)(hcur + bx * BB + b) + kq);

        ull acc[13];
        #pragma unroll
        for (int g = 0; g < 13; ++g) acc[g] = 0ULL;

        const int m0 = kq * MQ;
        #pragma unroll 2
        for (int mb = 0; mb < MQ / 4; ++mb) {
            int m = m0 + mb * 4;
            float4 f0 = __ldcg(hcur + (m + 0) * BB + b);
            float4 f1 = __ldcg(hcur + (m + 1) * BB + b);
            float4 f2 = __ldcg(hcur + (m + 2) * BB + b);
            float4 f3 = __ldcg(hcur + (m + 3) * BB + b);
            ull a0 = pack2(f0.x, f0.y), b0 = pack2(f0.z, f0.w);
            ull a1 = pack2(f1.x, f1.y), b1 = pack2(f1.z, f1.w);
            ull a2 = pack2(f2.x, f2.y), b2 = pack2(f2.z, f2.w);
            ull a3 = pack2(f3.x, f3.y), b3 = pack2(f3.z, f3.w);
            dot_block<12>(acc, s_w, m, a0, b0, a1, b1, a2, b2, a3, b3);
            const ulonglong2* lr = (const ulonglong2*)&s_lin[4 * m];
            ull t12 = acc[12];
            t12 = fma2(a0, lr[0].x, t12); t12 = fma2(b0, lr[0].y, t12);
            t12 = fma2(a1, lr[1].x, t12); t12 = fma2(b1, lr[1].y, t12);
            t12 = fma2(a2, lr[2].x, t12); t12 = fma2(b2, lr[2].y, t12);
            t12 = fma2(a3, lr[3].x, t12); t12 = fma2(b3, lr[3].y, t12);
            acc[12] = t12;
        }

        {
            float* dst = &s_red[(kq * 13) * BB + b];
            #pragma unroll
            for (int g = 0; g < 13; ++g) dst[g * BB] = red2(acc[g]);
        }
        __syncthreads();

        {
            float y = s_lb;
            #pragma unroll
            for (int qq = 0; qq < 4; ++qq) y += s_red[(qq * 13 + 12) * BB + b];
            if (i >= 1 && bx == 0 && kq == 0) out[b * TT + (TT - i)] = y;
            if (i < TT) {
                float ar = 0.f, az = 0.f, an = 0.f;
                #pragma unroll
                for (int qq = 0; qq < 4; ++qq) {
                    ar += s_red[(qq * 13 + g0 + 0) * BB + b];
                    az += s_red[(qq * 13 + g0 + 1) * BB + b];
                    an += s_red[(qq * 13 + g0 + 2) * BB + b];
                }
                float r = sigf(fmaf(y, s_wi[g0 + 0], s_bi[g0 + 0] + s_bh[g0 + 0]) + ar);
                float z = sigf(fmaf(y, s_wi[g0 + 1], s_bi[g0 + 1] + s_bh[g0 + 1]) + az);
                float n = ftanh(fmaf(y, s_wi[g0 + 2], s_bi[g0 + 2]) + r * (an + s_bh[g0 + 2]));
                ((float*)(hnxt + bx * BB + b))[kq] = (1.0f - z) * n + z * hp;
            }
        }

        if (i < TT) {
            grid_barrier();
            float4* tc = hcur; hcur = hnxt; hnxt = tc;
        }
    }
}

extern "C" void kernel_launch(void* const* d_in, const int* in_sizes, int n_in,
                              void* d_out, int out_size) {
    cudaFuncSetAttribute(gru_ae, cudaFuncAttributeMaxDynamicSharedMemorySize,
                         SMEM_BYTES);
    gru_ae<<<NBLK, NTH, SMEM_BYTES>>>(
        (const float*)d_in[0],
        (const float*)d_in[1], (const float*)d_in[2],
        (const float*)d_in[3], (const float*)d_in[4],
        (const float*)d_in[5], (const float*)d_in[6],
        (const float*)d_in[7], (const float*)d_in[8],
        (const float*)d_in[9], (const float*)d_in[10],
        (float*)d_out);
}

// round 13
// speedup vs baseline: 1.5553x; 1.2543x over previous
#include <cuda_runtime.h>

// GRU autoencoder: B=128, H=512, T=512 enc + 513 dec iterations.
// Persistent single kernel, 128 CTAs, CTA c owns hidden cols [4c,4c+4).
//
// R12 -> R13: each thread now owns TWO batches (b, b+64) over a 64-k octant
// (was: one batch over a 128-k quarter). Every 16B weight LDS feeds 4 fma2
// instead of 2 -> weight-LDS count halves (384->192/thread), LDS-latency
// exposure halves, fma2 (the fp32 floor) unchanged. Reduction: 8 partials
// per gate in SMEM. Epilogue mapping (col = tid>>7, b = tid&127) unchanged.

#define HH   512
#define TT   512
#define BB   128
#define NBLK 128
#define COLS 4
#define NTH  512

typedef unsigned long long ull;

#define SMEM_FLOATS (13 * HH + 8 * 13 * BB)   // weights+lin + s_red[8][13][BB]
#define SMEM_BYTES  (SMEM_FLOATS * 4)

__device__ float4 g_hA[HH * BB / 4];     // slot m*BB+b = h[4m..4m+3][b]
__device__ float4 g_hB[HH * BB / 4];
__device__ unsigned long long g_arrive;  // monotonic; replay-safe
__device__ unsigned long long g_release;

__device__ __forceinline__ void grid_barrier() {
    __threadfence();
    __syncthreads();
    if (threadIdx.x == 0) {
        unsigned long long t = atomicAdd(&g_arrive, 1ULL) + 1ULL;
        unsigned long long phase = (t + (unsigned long long)(NBLK - 1)) / NBLK;
        if ((t % NBLK) == 0ULL) {
            atomicAdd(&g_release, 1ULL);
        } else {
            long long guard = 0;
            while (*(volatile unsigned long long*)&g_release < phase) {
                __nanosleep(20);
                if (++guard > 900000000LL) __trap();
            }
        }
        __threadfence();
    }
    __syncthreads();
}

__device__ __forceinline__ float sigf(float v) {
    return __fdividef(1.0f, 1.0f + __expf(-v));
}
__device__ __forceinline__ float ftanh(float v) {
    float e = __expf(-2.0f * v);
    return __fdividef(1.0f - e, 1.0f + e);
}

__device__ __forceinline__ ull pack2(float lo, float hi) {
    ull r;
    asm("mov.b64 %0, {%1, %2};" : "=l"(r) : "f"(lo), "f"(hi));
    return r;
}
__device__ __forceinline__ ull fma2(ull a, ull b, ull c) {
    ull d;
    asm("fma.rn.f32x2 %0, %1, %2, %3;" : "=l"(d) : "l"(a), "l"(b), "l"(c));
    return d;
}
__device__ __forceinline__ float red2(ull v) {
    float lo, hi;
    asm("mov.b64 {%0, %1}, %2;" : "=f"(lo), "=f"(hi) : "l"(v));
    return lo + hi;
}

__global__ void __launch_bounds__(NTH, 1)
gru_ae(const float* __restrict__ x,
       const float* __restrict__ eWi, const float* __restrict__ eWh,
       const float* __restrict__ ebi, const float* __restrict__ ebh,
       const float* __restrict__ dWi, const float* __restrict__ dWh,
       const float* __restrict__ dbi, const float* __restrict__ dbh,
       const float* __restrict__ lW,  const float* __restrict__ lb,
       float* __restrict__ out)
{
    extern __shared__ __align__(16) float smem[];
    float* s_w   = smem;                 // 12*HH: Wh rows, row = col*3+gate
    float* s_lin = smem + 12 * HH;       // HH
    float* s_red = smem + 13 * HH;       // [ko 8][13][BB]

    __shared__ float s_wi[12], s_bi[12], s_bh[12];
    __shared__ float s_lb;

    const int tid  = threadIdx.x;
    const int bx   = blockIdx.x;
    const int j0   = bx * COLS;

    // mainloop mapping: two batches per thread, 64-k octant
    const int lane = tid & 31;
    const int wrp  = tid >> 5;           // 0..15
    const int bA   = lane + 32 * (wrp & 1);
    const int bB   = bA + 64;
    const int ko   = wrp >> 1;           // 0..7
    const int m0   = ko * 16;            // float4-slot base (16 slots = 64 k)

    // epilogue mapping: one (col, b) output per thread
    const int eb   = tid & (BB - 1);
    const int ec   = tid >> 7;           // 0..3
    const int g0   = 3 * ec;

    // ---- encoder weights -> SMEM ----
    for (int i = tid; i < 12 * (HH / 4); i += NTH) {
        int gl = i / (HH / 4), kk = i % (HH / 4);
        int grow = (gl % 3) * HH + (j0 + gl / 3);
        ((float4*)s_w)[gl * (HH / 4) + kk] = ((const float4*)eWh)[grow * (HH / 4) + kk];
    }
    for (int i = tid; i < HH / 4; i += NTH)
        ((float4*)s_lin)[i] = ((const float4*)lW)[i];
    if (tid < 12) {
        int grow = (tid % 3) * HH + (j0 + tid / 3);
        s_wi[tid] = eWi[grow];
        s_bi[tid] = ebi[grow];
        s_bh[tid] = ebh[grow];
    }
    if (tid == 0) s_lb = lb[0];

    if (tid < BB) g_hA[bx * BB + tid] = make_float4(0.f, 0.f, 0.f, 0.f);

    grid_barrier();

    float4* hcur = g_hA;
    float4* hnxt = g_hB;

    // ================= encoder: 512 steps =================
    for (int t = 0; t < TT; ++t) {
        float hp = __ldcg((const float*)(hcur + bx * BB + eb) + ec);
        float xv = x[eb * TT + t];

        ull accA[12], accB[12];
        #pragma unroll
        for (int g = 0; g < 12; ++g) { accA[g] = 0ULL; accB[g] = 0ULL; }

        #pragma unroll 2
        for (int mb = 0; mb < 4; ++mb) {
            const int m = m0 + mb * 4;
            float4 fA0 = __ldcg(hcur + (m + 0) * BB + bA);
            float4 fB0 = __ldcg(hcur + (m + 0) * BB + bB);
            float4 fA1 = __ldcg(hcur + (m + 1) * BB + bA);
            float4 fB1 = __ldcg(hcur + (m + 1) * BB + bB);
            float4 fA2 = __ldcg(hcur + (m + 2) * BB + bA);
            float4 fB2 = __ldcg(hcur + (m + 2) * BB + bB);
            float4 fA3 = __ldcg(hcur + (m + 3) * BB + bA);
            float4 fB3 = __ldcg(hcur + (m + 3) * BB + bB);
            ull hA[8] = { pack2(fA0.x, fA0.y), pack2(fA0.z, fA0.w),
                          pack2(fA1.x, fA1.y), pack2(fA1.z, fA1.w),
                          pack2(fA2.x, fA2.y), pack2(fA2.z, fA2.w),
                          pack2(fA3.x, fA3.y), pack2(fA3.z, fA3.w) };
            ull hB[8] = { pack2(fB0.x, fB0.y), pack2(fB0.z, fB0.w),
                          pack2(fB1.x, fB1.y), pack2(fB1.z, fB1.w),
                          pack2(fB2.x, fB2.y), pack2(fB2.z, fB2.w),
                          pack2(fB3.x, fB3.y), pack2(fB3.z, fB3.w) };
            #pragma unroll
            for (int g = 0; g < 12; ++g) {
                const ulonglong2* wr = (const ulonglong2*)&s_w[g * HH + 4 * m];
                ull tA = accA[g], tB = accB[g];
                #pragma unroll
                for (int s = 0; s < 4; ++s) {
                    ulonglong2 w2 = wr[s];
                    tA = fma2(hA[2 * s + 0], w2.x, tA);
                    tB = fma2(hB[2 * s + 0], w2.x, tB);
                    tA = fma2(hA[2 * s + 1], w2.y, tA);
                    tB = fma2(hB[2 * s + 1], w2.y, tB);
                }
                accA[g] = tA; accB[g] = tB;
            }
        }

        // publish 8-way partials
        {
            #pragma unroll
            for (int g = 0; g < 12; ++g) {
                float* base = &s_red[(ko * 13 + g) * BB];
                base[bA] = red2(accA[g]);
                base[bB] = red2(accB[g]);
            }
        }
        __syncthreads();

        // epilogue: thread owns (col=ec, batch=eb)
        {
            float ar = 0.f, az = 0.f, an = 0.f;
            #pragma unroll
            for (int q = 0; q < 8; ++q) {
                ar += s_red[(q * 13 + g0 + 0) * BB + eb];
                az += s_red[(q * 13 + g0 + 1) * BB + eb];
                an += s_red[(q * 13 + g0 + 2) * BB + eb];
            }
            float r = sigf(fmaf(xv, s_wi[g0 + 0], s_bi[g0 + 0] + s_bh[g0 + 0]) + ar);
            float z = sigf(fmaf(xv, s_wi[g0 + 1], s_bi[g0 + 1] + s_bh[g0 + 1]) + az);
            float n = ftanh(fmaf(xv, s_wi[g0 + 2], s_bi[g0 + 2]) + r * (an + s_bh[g0 + 2]));
            ((float*)(hnxt + bx * BB + eb))[ec] = (1.0f - z) * n + z * hp;
        }

        grid_barrier();
        float4* tc = hcur; hcur = hnxt; hnxt = tc;
    }

    // ---- swap SMEM weights to decoder ----
    for (int i = tid; i < 12 * (HH / 4); i += NTH) {
        int gl = i / (HH / 4), kk = i % (HH / 4);
        int grow = (gl % 3) * HH + (j0 + gl / 3);
        ((float4*)s_w)[gl * (HH / 4) + kk] = ((const float4*)dWh)[grow * (HH / 4) + kk];
    }
    if (tid < 12) {
        int grow = (tid % 3) * HH + (j0 + tid / 3);
        s_wi[tid] = dWi[grow];
        s_bi[tid] = dbi[grow];
        s_bh[tid] = dbh[grow];
    }
    __syncthreads();

    // ================= decoder: i = 0..512 =================
    // y_i = h_i @ lin_W.T + lin_b (13th acc, redundant per CTA). Emit y_i at
    // out[:, T-i] for i>=1. For i<512 also compute h_{i+1}.
    for (int i = 0; i <= TT; ++i) {
        float hp = __ldcg((const float*)(hcur + bx * BB + eb) + ec);

        ull accA[13], accB[13];
        #pragma unroll
        for (int g = 0; g < 13; ++g) { accA[g] = 0ULL; accB[g] = 0ULL; }

        #pragma unroll 2
        for (int mb = 0; mb < 4; ++mb) {
            const int m = m0 + mb * 4;
            float4 fA0 = __ldcg(hcur + (m + 0) * BB + bA);
            float4 fB0 = __ldcg(hcur + (m + 0) * BB + bB);
            float4 fA1 = __ldcg(hcur + (m + 1) * BB + bA);
            float4 fB1 = __ldcg(hcur + (m + 1) * BB + bB);
            float4 fA2 = __ldcg(hcur + (m + 2) * BB + bA);
            float4 fB2 = __ldcg(hcur + (m + 2) * BB + bB);
            float4 fA3 = __ldcg(hcur + (m + 3) * BB + bA);
            float4 fB3 = __ldcg(hcur + (m + 3) * BB + bB);
            ull hA[8] = { pack2(fA0.x, fA0.y), pack2(fA0.z, fA0.w),
                          pack2(fA1.x, fA1.y), pack2(fA1.z, fA1.w),
                          pack2(fA2.x, fA2.y), pack2(fA2.z, fA2.w),
                          pack2(fA3.x, fA3.y), pack2(fA3.z, fA3.w) };
            ull hB[8] = { pack2(fB0.x, fB0.y), pack2(fB0.z, fB0.w),
                          pack2(fB1.x, fB1.y), pack2(fB1.z, fB1.w),
                          pack2(fB2.x, fB2.y), pack2(fB2.z, fB2.w),
                          pack2(fB3.x, fB3.y), pack2(fB3.z, fB3.w) };
            #pragma unroll
            for (int g = 0; g < 12; ++g) {
                const ulonglong2* wr = (const ulonglong2*)&s_w[g * HH + 4 * m];
                ull tA = accA[g], tB = accB[g];
                #pragma unroll
                for (int s = 0; s < 4; ++s) {
                    ulonglong2 w2 = wr[s];
                    tA = fma2(hA[2 * s + 0], w2.x, tA);
                    tB = fma2(hB[2 * s + 0], w2.x, tB);
                    tA = fma2(hA[2 * s + 1], w2.y, tA);
                    tB = fma2(hB[2 * s + 1], w2.y, tB);
                }
                accA[g] = tA; accB[g] = tB;
            }
            {
                const ulonglong2* lr = (const ulonglong2*)&s_lin[4 * m];
                ull tA = accA[12], tB = accB[12];
                #pragma unroll
                for (int s = 0; s < 4; ++s) {
                    ulonglong2 w2 = lr[s];
                    tA = fma2(hA[2 * s + 0], w2.x, tA);
                    tB = fma2(hB[2 * s + 0], w2.x, tB);
                    tA = fma2(hA[2 * s + 1], w2.y, tA);
                    tB = fma2(hB[2 * s + 1], w2.y, tB);
                }
                accA[12] = tA; accB[12] = tB;
            }
        }

        {
            #pragma unroll
            for (int g = 0; g < 13; ++g) {
                float* base = &s_red[(ko * 13 + g) * BB];
                base[bA] = red2(accA[g]);
                base[bB] = red2(accB[g]);
            }
        }
        __syncthreads();

        {
            float y = s_lb;
            #pragma unroll
            for (int q = 0; q < 8; ++q) y += s_red[(q * 13 + 12) * BB + eb];
            if (i >= 1 && bx == 0 && ec == 0) out[eb * TT + (TT - i)] = y;
            if (i < TT) {
                float ar = 0.f, az = 0.f, an = 0.f;
                #pragma unroll
                for (int q = 0; q < 8; ++q) {
                    ar += s_red[(q * 13 + g0 + 0) * BB + eb];
                    az += s_red[(q * 13 + g0 + 1) * BB + eb];
                    an += s_red[(q * 13 + g0 + 2) * BB + eb];
                }
                float r = sigf(fmaf(y, s_wi[g0 + 0], s_bi[g0 + 0] + s_bh[g0 + 0]) + ar);
                float z = sigf(fmaf(y, s_wi[g0 + 1], s_bi[g0 + 1] + s_bh[g0 + 1]) + az);
                float n = ftanh(fmaf(y, s_wi[g0 + 2], s_bi[g0 + 2]) + r * (an + s_bh[g0 + 2]));
                ((float*)(hnxt + bx * BB + eb))[ec] = (1.0f - z) * n + z * hp;
            }
        }

        if (i < TT) {
            grid_barrier();
            float4* tc = hcur; hcur = hnxt; hnxt = tc;
        }
    }
}

extern "C" void kernel_launch(void* const* d_in, const int* in_sizes, int n_in,
                              void* d_out, int out_size) {
    cudaFuncSetAttribute(gru_ae, cudaFuncAttributeMaxDynamicSharedMemorySize,
                         SMEM_BYTES);
    gru_ae<<<NBLK, NTH, SMEM_BYTES>>>(
        (const float*)d_in[0],
        (const float*)d_in[1], (const float*)d_in[2],
        (const float*)d_in[3], (const float*)d_in[4],
        (const float*)d_in[5], (const float*)d_in[6],
        (const float*)d_in[7], (const float*)d_in[8],
        (const float*)d_in[9], (const float*)d_in[10],
        (float*)d_out);
}